// round 1
// baseline (speedup 1.0000x reference)
#include <cuda_runtime.h>
#include <math.h>

#define T_TOKENS 8192
#define D        4096
#define NS       4
#define HID      1024
#define NW       24      // 4 pre + 4 post + 16 res
#define KT       256
#define TOKB     8
#define TAU_INV  20.0f   // 1/0.05
#define EPS_W    1e-6f

// ---- scratch (static device globals; allowed) ----
__device__ float g_xlayer[T_TOKENS * HID];
__device__ float g_y[T_TOKENS * HID];
__device__ float g_Hpost[T_TOKENS * NS];
__device__ float g_Hres[T_TOKENS * NS * NS];

__device__ __forceinline__ float lse4(float a0, float a1, float a2, float a3) {
    float m = fmaxf(fmaxf(a0, a1), fmaxf(a2, a3));
    float s = __expf(a0 - m) + __expf(a1 - m) + __expf(a2 - m) + __expf(a3 - m);
    return m + __logf(s);
}

// ============================================================
// Kernel 1: per-token gates + sinkhorn + x_layer
//   Each block handles TOKB=8 tokens.
// ============================================================
__global__ __launch_bounds__(256, 4)
void gates_kernel(const float* __restrict__ x,
                  const float* __restrict__ rmsw,
                  const float* __restrict__ Wpre,
                  const float* __restrict__ Wpost,
                  const float* __restrict__ Wres,
                  const float* __restrict__ bpre,
                  const float* __restrict__ bpost,
                  const float* __restrict__ bres,
                  const float* __restrict__ apre,
                  const float* __restrict__ apost,
                  const float* __restrict__ ares)
{
    __shared__ __align__(16) float s_w[KT * 25];       // [j][k], padded
    __shared__ __align__(16) float s_x[TOKB * KT];     // [g][j]
    __shared__ float s_dots[TOKB][NW];
    __shared__ float s_inv[TOKB];
    __shared__ float s_hpre[TOKB][NS];

    const int tid  = threadIdx.x;
    const int warp = tid >> 5, lane = tid & 31;
    const long t0  = (long)blockIdx.x * TOKB;

    // ---- pass 1: per-token rsqrt(mean(x^2)+eps); warp w -> token w ----
    {
        const float4* xr = (const float4*)(x + (t0 + warp) * D);
        float ss = 0.f;
        #pragma unroll 4
        for (int i = lane; i < D / 4; i += 32) {
            float4 v = xr[i];
            ss += v.x * v.x + v.y * v.y + v.z * v.z + v.w * v.w;
        }
        #pragma unroll
        for (int o = 16; o; o >>= 1) ss += __shfl_xor_sync(0xffffffffu, ss, o);
        if (lane == 0) s_inv[warp] = rsqrtf(ss * (1.0f / D) + 1e-8f);
    }

    // ---- pass 2: 24 dot products per token (rms weight folded into W tile) ----
    float acc = 0.f;
    const int g = tid / NW, k = tid % NW;   // valid for tid < 192

    for (int kt = 0; kt < D / KT; kt++) {
        const int k0 = kt * KT;
        __syncthreads();
        // load W tile transposed, scaled by rms weight
        {
            const float rw = rmsw[k0 + tid];
            #pragma unroll
            for (int m = 0; m < NW; m++) {
                const float* Wr = (m < 4) ? (Wpre + m * D)
                                 : (m < 8) ? (Wpost + (m - 4) * D)
                                           : (Wres + (m - 8) * D);
                s_w[tid * 25 + m] = Wr[k0 + tid] * rw;
            }
            // load x tile: 8 tokens x 256 floats = 512 float4
            #pragma unroll
            for (int m = 0; m < 2; m++) {
                int i  = tid + m * 256;
                int gg = i >> 6, j4 = i & 63;
                ((float4*)s_x)[i] =
                    ((const float4*)(x + (t0 + gg) * D + k0))[j4];
            }
        }
        __syncthreads();
        if (tid < TOKB * NW) {
            const float* xs = s_x + g * KT;
            #pragma unroll 8
            for (int j = 0; j < KT; j++)
                acc = fmaf(xs[j], s_w[j * 25 + k], acc);
        }
    }
    __syncthreads();
    if (tid < TOKB * NW) s_dots[g][k] = acc;
    __syncthreads();

    // ---- gate math: warp 0, 4 lanes per token ----
    if (tid < 32) {
        const int tt = lane >> 2, r = lane & 3;
        const int base = lane & ~3;
        const long t = t0 + tt;
        const float inv = s_inv[tt];
        const float a_pre = apre[0], a_post = apost[0], a_res = ares[0];

        // H_pre
        float zp = fmaf(a_pre, inv * s_dots[tt][r], bpre[r]);
        float hp = 1.0f / (1.0f + __expf(-zp));
        float sp = hp;
        sp += __shfl_xor_sync(0xffffffffu, sp, 1);
        sp += __shfl_xor_sync(0xffffffffu, sp, 2);
        s_hpre[tt][r] = hp / (sp + EPS_W);

        // H_post
        float zq = fmaf(a_post, inv * s_dots[tt][4 + r], bpost[r]);
        float hq = 2.0f / (1.0f + __expf(-zq));
        float sq = hq;
        sq += __shfl_xor_sync(0xffffffffu, sq, 1);
        sq += __shfl_xor_sync(0xffffffffu, sq, 2);
        g_Hpost[t * NS + r] = hq / (sq + EPS_W);

        // Sinkhorn (log domain), lane r owns row r (u_r) and col r (v_r)
        float Zrow[4], Zcol[4];
        #pragma unroll
        for (int i = 0; i < 4; i++) {
            Zrow[i] = fmaf(a_res, inv * s_dots[tt][8 + r * 4 + i], bres[r * 4 + i]) * TAU_INV;
            Zcol[i] = fmaf(a_res, inv * s_dots[tt][8 + i * 4 + r], bres[i * 4 + r]) * TAU_INV;
        }
        float ur = 0.f, vr = 0.f;
        for (int it = 0; it < 20; it++) {
            float v0 = __shfl_sync(0xffffffffu, vr, base + 0);
            float v1 = __shfl_sync(0xffffffffu, vr, base + 1);
            float v2 = __shfl_sync(0xffffffffu, vr, base + 2);
            float v3 = __shfl_sync(0xffffffffu, vr, base + 3);
            ur = -lse4(Zrow[0] + v0, Zrow[1] + v1, Zrow[2] + v2, Zrow[3] + v3);
            float u0 = __shfl_sync(0xffffffffu, ur, base + 0);
            float u1 = __shfl_sync(0xffffffffu, ur, base + 1);
            float u2 = __shfl_sync(0xffffffffu, ur, base + 2);
            float u3 = __shfl_sync(0xffffffffu, ur, base + 3);
            vr = -lse4(Zcol[0] + u0, Zcol[1] + u1, Zcol[2] + u2, Zcol[3] + u3);
        }
        float v0 = __shfl_sync(0xffffffffu, vr, base + 0);
        float v1 = __shfl_sync(0xffffffffu, vr, base + 1);
        float v2 = __shfl_sync(0xffffffffu, vr, base + 2);
        float v3 = __shfl_sync(0xffffffffu, vr, base + 3);
        g_Hres[t * 16 + r * 4 + 0] = __expf(Zrow[0] + ur + v0);
        g_Hres[t * 16 + r * 4 + 1] = __expf(Zrow[1] + ur + v1);
        g_Hres[t * 16 + r * 4 + 2] = __expf(Zrow[2] + ur + v2);
        g_Hres[t * 16 + r * 4 + 3] = __expf(Zrow[3] + ur + v3);
    }
    __syncthreads();

    // ---- pass 3: x_layer[t,c] = sum_n Hpre_w[n] * x[t,n,c] ----
    #pragma unroll
    for (int gg = 0; gg < TOKB; gg++) {
        const long t = t0 + gg;
        const float h0 = s_hpre[gg][0], h1 = s_hpre[gg][1];
        const float h2 = s_hpre[gg][2], h3 = s_hpre[gg][3];
        const float4* xr = (const float4*)(x + t * D);
        float4 a = xr[tid], b = xr[256 + tid], c = xr[512 + tid], e = xr[768 + tid];
        float4 o;
        o.x = h0 * a.x + h1 * b.x + h2 * c.x + h3 * e.x;
        o.y = h0 * a.y + h1 * b.y + h2 * c.y + h3 * e.y;
        o.z = h0 * a.z + h1 * b.z + h2 * c.z + h3 * e.z;
        o.w = h0 * a.w + h1 * b.w + h2 * c.w + h3 * e.w;
        ((float4*)g_xlayer)[t * 256 + tid] = o;
    }
}

// ============================================================
// Kernel 2: y = x_layer @ W_sub^T   (fp32 SIMT tiled GEMM)
//   128x128 block tile, BK=8, 8x8 per thread
// ============================================================
#define BM 128
#define BN 128
#define BK 8
__global__ __launch_bounds__(256, 2)
void gemm_kernel(const float* __restrict__ A,   // [8192,1024]
                 const float* __restrict__ Bw,  // [1024,1024] (row-major N,K)
                 float* __restrict__ Cy)        // [8192,1024]
{
    __shared__ __align__(16) float s_a[BK][BM];
    __shared__ __align__(16) float s_b[BK][BN];
    const int tid = threadIdx.x;
    const int m0 = blockIdx.y * BM, n0 = blockIdx.x * BN;
    const int tx = tid & 15, ty = tid >> 4;
    const int lr = tid >> 1, lk = (tid & 1) * 4;

    float acc[8][8];
    #pragma unroll
    for (int i = 0; i < 8; i++)
        #pragma unroll
        for (int j = 0; j < 8; j++) acc[i][j] = 0.f;

    for (int k0 = 0; k0 < HID; k0 += BK) {
        float4 av = *(const float4*)(A  + (long)(m0 + lr) * HID + k0 + lk);
        float4 bv = *(const float4*)(Bw + (long)(n0 + lr) * HID + k0 + lk);
        __syncthreads();
        s_a[lk + 0][lr] = av.x; s_a[lk + 1][lr] = av.y;
        s_a[lk + 2][lr] = av.z; s_a[lk + 3][lr] = av.w;
        s_b[lk + 0][lr] = bv.x; s_b[lk + 1][lr] = bv.y;
        s_b[lk + 2][lr] = bv.z; s_b[lk + 3][lr] = bv.w;
        __syncthreads();
        #pragma unroll
        for (int kk = 0; kk < BK; kk++) {
            float4 a0 = *(const float4*)&s_a[kk][ty * 8];
            float4 a1 = *(const float4*)&s_a[kk][ty * 8 + 4];
            float4 b0 = *(const float4*)&s_b[kk][tx * 8];
            float4 b1 = *(const float4*)&s_b[kk][tx * 8 + 4];
            float ar[8] = {a0.x, a0.y, a0.z, a0.w, a1.x, a1.y, a1.z, a1.w};
            float br[8] = {b0.x, b0.y, b0.z, b0.w, b1.x, b1.y, b1.z, b1.w};
            #pragma unroll
            for (int i = 0; i < 8; i++)
                #pragma unroll
                for (int j = 0; j < 8; j++)
                    acc[i][j] = fmaf(ar[i], br[j], acc[i][j]);
        }
    }
    #pragma unroll
    for (int i = 0; i < 8; i++) {
        float4* out = (float4*)(Cy + (long)(m0 + ty * 8 + i) * HID + n0 + tx * 8);
        out[0] = make_float4(acc[i][0], acc[i][1], acc[i][2], acc[i][3]);
        out[1] = make_float4(acc[i][4], acc[i][5], acc[i][6], acc[i][7]);
    }
}

// ============================================================
// Kernel 3: out[t,o,c] = sum_i Hres[t,o,i]*x[t,i,c] + Hpost_w[t,o]*y[t,c]
// ============================================================
__global__ __launch_bounds__(256)
void mix_kernel(const float* __restrict__ x, float* __restrict__ out)
{
    const long t = blockIdx.x;
    const int tid = threadIdx.x;
    __shared__ float s_h[16];
    __shared__ float s_p[4];
    if (tid < 16) s_h[tid] = g_Hres[t * 16 + tid];
    if (tid < 4)  s_p[tid] = g_Hpost[t * 4 + tid];
    __syncthreads();

    const float4* xr = (const float4*)(x + t * D);
    const float4* yr = (const float4*)(g_y + t * HID);
    float4* op = (float4*)(out + t * D);

    float4 xi0 = xr[tid], xi1 = xr[256 + tid], xi2 = xr[512 + tid], xi3 = xr[768 + tid];
    float4 y4 = yr[tid];

    #pragma unroll
    for (int o = 0; o < 4; o++) {
        float h0 = s_h[o * 4 + 0], h1 = s_h[o * 4 + 1];
        float h2 = s_h[o * 4 + 2], h3 = s_h[o * 4 + 3];
        float p = s_p[o];
        float4 r;
        r.x = h0 * xi0.x + h1 * xi1.x + h2 * xi2.x + h3 * xi3.x + p * y4.x;
        r.y = h0 * xi0.y + h1 * xi1.y + h2 * xi2.y + h3 * xi3.y + p * y4.y;
        r.z = h0 * xi0.z + h1 * xi1.z + h2 * xi2.z + h3 * xi3.z + p * y4.z;
        r.w = h0 * xi0.w + h1 * xi1.w + h2 * xi2.w + h3 * xi3.w + p * y4.w;
        op[o * 256 + tid] = r;
    }
}

// ============================================================
extern "C" void kernel_launch(void* const* d_in, const int* in_sizes, int n_in,
                              void* d_out, int out_size)
{
    const float* x      = (const float*)d_in[0];
    const float* rmsw   = (const float*)d_in[1];
    const float* Wpre   = (const float*)d_in[2];
    const float* Wpost  = (const float*)d_in[3];
    const float* Wres   = (const float*)d_in[4];
    const float* bpre   = (const float*)d_in[5];
    const float* bpost  = (const float*)d_in[6];
    const float* bres   = (const float*)d_in[7];
    const float* apre   = (const float*)d_in[8];
    const float* apost  = (const float*)d_in[9];
    const float* ares   = (const float*)d_in[10];
    const float* Wsub   = (const float*)d_in[11];
    float* out = (float*)d_out;

    float* xlayer_p; cudaGetSymbolAddress((void**)&xlayer_p, g_xlayer);
    float* y_p;      cudaGetSymbolAddress((void**)&y_p, g_y);

    gates_kernel<<<T_TOKENS / TOKB, 256>>>(x, rmsw, Wpre, Wpost, Wres,
                                           bpre, bpost, bres, apre, apost, ares);
    gemm_kernel<<<dim3(HID / BN, T_TOKENS / BM), 256>>>(xlayer_p, Wsub, y_p);
    mix_kernel<<<T_TOKENS, 256>>>(x, out);
}

// round 3
// speedup vs baseline: 2.3071x; 2.3071x over previous
#include <cuda_runtime.h>
#include <cuda_bf16.h>
#include <cstdint>
#include <math.h>

#define T_TOKENS 8192
#define D        4096
#define NS       4
#define HID      1024
#define NW       24
#define KT       128
#define TOKB     16
#define TAU_INV  20.0f
#define EPS_W    1e-6f

// ================= scratch =================
__device__ __nv_bfloat16 g_xhi[T_TOKENS * HID];
__device__ __nv_bfloat16 g_xlo[T_TOKENS * HID];
__device__ __nv_bfloat16 g_whi[HID * HID];
__device__ __nv_bfloat16 g_wlo[HID * HID];
__device__ float g_y[T_TOKENS * HID];
__device__ float g_Hpost[T_TOKENS * NS];
__device__ float g_Hres[T_TOKENS * NS * NS];

// ================= helpers =================
__device__ __forceinline__ uint32_t smem_to_u32(const void* p) {
    uint32_t a;
    asm("{ .reg .u64 t; cvta.to.shared.u64 t, %1; cvt.u32.u64 %0, t; }" : "=r"(a) : "l"(p));
    return a;
}
__device__ __forceinline__ void cp16(uint32_t s, const void* g) {
    asm volatile("cp.async.cg.shared.global [%0], [%1], 16;" :: "r"(s), "l"(g));
}
__device__ __forceinline__ void ldsm_x4(uint32_t& r0, uint32_t& r1, uint32_t& r2,
                                        uint32_t& r3, uint32_t addr) {
    asm volatile("ldmatrix.sync.aligned.m8n8.x4.shared.b16 {%0,%1,%2,%3}, [%4];"
                 : "=r"(r0), "=r"(r1), "=r"(r2), "=r"(r3) : "r"(addr));
}
__device__ __forceinline__ void mma16816(float* c, const uint32_t* a, const uint32_t* b) {
    asm volatile(
        "mma.sync.aligned.m16n8k16.row.col.f32.bf16.bf16.f32 "
        "{%0,%1,%2,%3}, {%4,%5,%6,%7}, {%8,%9}, {%0,%1,%2,%3};"
        : "+f"(c[0]), "+f"(c[1]), "+f"(c[2]), "+f"(c[3])
        : "r"(a[0]), "r"(a[1]), "r"(a[2]), "r"(a[3]), "r"(b[0]), "r"(b[1]));
}
#define SW128(off) ((off) ^ (((off) >> 3) & 0x70))

__device__ __forceinline__ float lse4(float a0, float a1, float a2, float a3) {
    float m = fmaxf(fmaxf(a0, a1), fmaxf(a2, a3));
    float s = __expf(a0 - m) + __expf(a1 - m) + __expf(a2 - m) + __expf(a3 - m);
    return m + __logf(s);
}
__device__ __forceinline__ uint32_t pack2bf(float a, float b) {
    __nv_bfloat162 t = __floats2bfloat162_rn(a, b);
    return *(uint32_t*)&t;
}

// ============================================================
// Kernel 1: gates + sinkhorn + x_layer (bf16 hi/lo out)
//   16 tokens/block, 256 threads.
// ============================================================
__global__ __launch_bounds__(256, 4)
void gates_kernel(const float* __restrict__ x,
                  const float* __restrict__ rmsw,
                  const float* __restrict__ Wpre,
                  const float* __restrict__ Wpost,
                  const float* __restrict__ Wres,
                  const float* __restrict__ bpre,
                  const float* __restrict__ bpost,
                  const float* __restrict__ bres,
                  const float* __restrict__ apre,
                  const float* __restrict__ apost,
                  const float* __restrict__ ares)
{
    __shared__ __align__(16) float s_x[TOKB * KT];        // 8KB, row=128 floats
    __shared__ __align__(16) float s_w[NW * 132];         // 12.7KB, row=132 floats
    __shared__ float s_dots[TOKB][NW];
    __shared__ float s_ssq[TOKB];
    __shared__ float s_inv[TOKB];
    __shared__ float s_hpre[TOKB][NS];

    const int tid  = threadIdx.x;
    const int lane = tid & 31;
    const long t0  = (long)blockIdx.x * TOKB;

    // thread mapping for dot compute
    const int ks = tid & 3;            // k quarter (32 floats each)
    const int mt = (tid >> 2) & 7;     // m triple
    const int tp = tid >> 5;           // token pair (2tp, 2tp+1)

    float acc[2][3] = {{0.f,0.f,0.f},{0.f,0.f,0.f}};
    float ss0 = 0.f, ss1 = 0.f;        // tokens tid>>5 and tid>>5 + 8

    for (int kt = 0; kt < D / KT; kt++) {
        const int k0 = kt * KT;
        __syncthreads();
        // load W tile (folded with rms weight)
        #pragma unroll
        for (int j = 0; j < 12; j++) {
            int i = tid + j * 256;          // 0..3071
            int m = i >> 7, k = i & 127;
            const float* Wr = (m < 4) ? (Wpre + m * D)
                             : (m < 8) ? (Wpost + (m - 4) * D)
                                       : (Wres + (m - 8) * D);
            s_w[m * 132 + k] = Wr[k0 + k] * rmsw[k0 + k];
        }
        // load x tile + accumulate sumsq
        {
            int i0 = tid;                   // tok = tid>>5, k4 = tid&31
            float4 v = ((const float4*)(x + (t0 + (i0 >> 5)) * D + k0))[i0 & 31];
            ((float4*)s_x)[(i0 >> 5) * 32 + (i0 & 31)] = v;
            ss0 += v.x*v.x + v.y*v.y + v.z*v.z + v.w*v.w;
            int i1 = tid + 256;
            float4 u = ((const float4*)(x + (t0 + (i1 >> 5)) * D + k0))[i1 & 31];
            ((float4*)s_x)[(i1 >> 5) * 32 + (i1 & 31)] = u;
            ss1 += u.x*u.x + u.y*u.y + u.z*u.z + u.w*u.w;
        }
        __syncthreads();
        // dot compute: 2 tokens x 3 m's, k range [ks*32, ks*32+32)
        const float4* x4a = (const float4*)s_x + (2 * tp) * 32;
        const float4* x4b = x4a + 32;
        #pragma unroll
        for (int kk = 0; kk < 8; kk++) {
            int k4 = ks * 8 + ((kk + 2 * ks) & 7);
            float4 xa = x4a[k4];
            float4 xb = x4b[k4];
            #pragma unroll
            for (int j = 0; j < 3; j++) {
                float4 w = ((const float4*)s_w)[(3 * mt + j) * 33 + k4];
                acc[0][j] = fmaf(xa.x, w.x, fmaf(xa.y, w.y, fmaf(xa.z, w.z, fmaf(xa.w, w.w, acc[0][j]))));
                acc[1][j] = fmaf(xb.x, w.x, fmaf(xb.y, w.y, fmaf(xb.z, w.z, fmaf(xb.w, w.w, acc[1][j]))));
            }
        }
    }

    // sumsq reduce (warp w owns tokens w and w+8 exclusively)
    #pragma unroll
    for (int o = 16; o; o >>= 1) {
        ss0 += __shfl_xor_sync(0xffffffffu, ss0, o);
        ss1 += __shfl_xor_sync(0xffffffffu, ss1, o);
    }
    if (lane == 0) { s_ssq[tp] = ss0; s_ssq[tp + 8] = ss1; }

    // k-split reduce over ks (lanes differ in bits 0-1)
    #pragma unroll
    for (int i = 0; i < 2; i++)
        #pragma unroll
        for (int j = 0; j < 3; j++) {
            float a = acc[i][j];
            a += __shfl_xor_sync(0xffffffffu, a, 1);
            a += __shfl_xor_sync(0xffffffffu, a, 2);
            acc[i][j] = a;
        }
    __syncthreads();
    if (ks == 0) {
        #pragma unroll
        for (int i = 0; i < 2; i++)
            #pragma unroll
            for (int j = 0; j < 3; j++)
                s_dots[2 * tp + i][3 * mt + j] = acc[i][j];
    }
    if (tid < TOKB) s_inv[tid] = rsqrtf(s_ssq[tid] * (1.0f / D) + 1e-8f);
    __syncthreads();

    // ---- gate math: 2 warps, 4 lanes per token ----
    if (tid < 64) {
        const int w2 = tid >> 5;
        const int tt = w2 * 8 + (lane >> 2), r = lane & 3;
        const int base = lane & ~3;
        const long t = t0 + tt;
        const float inv = s_inv[tt];
        const float a_pre = apre[0], a_post = apost[0], a_res = ares[0];

        float zp = fmaf(a_pre, inv * s_dots[tt][r], bpre[r]);
        float hp = 1.0f / (1.0f + __expf(-zp));
        float sp = hp;
        sp += __shfl_xor_sync(0xffffffffu, sp, 1);
        sp += __shfl_xor_sync(0xffffffffu, sp, 2);
        s_hpre[tt][r] = hp / (sp + EPS_W);

        float zq = fmaf(a_post, inv * s_dots[tt][4 + r], bpost[r]);
        float hq = 2.0f / (1.0f + __expf(-zq));
        float sq = hq;
        sq += __shfl_xor_sync(0xffffffffu, sq, 1);
        sq += __shfl_xor_sync(0xffffffffu, sq, 2);
        g_Hpost[t * NS + r] = hq / (sq + EPS_W);

        float Zrow[4], Zcol[4];
        #pragma unroll
        for (int i = 0; i < 4; i++) {
            Zrow[i] = fmaf(a_res, inv * s_dots[tt][8 + r * 4 + i], bres[r * 4 + i]) * TAU_INV;
            Zcol[i] = fmaf(a_res, inv * s_dots[tt][8 + i * 4 + r], bres[i * 4 + r]) * TAU_INV;
        }
        float ur = 0.f, vr = 0.f;
        for (int it = 0; it < 20; it++) {
            float v0 = __shfl_sync(0xffffffffu, vr, base + 0);
            float v1 = __shfl_sync(0xffffffffu, vr, base + 1);
            float v2 = __shfl_sync(0xffffffffu, vr, base + 2);
            float v3 = __shfl_sync(0xffffffffu, vr, base + 3);
            ur = -lse4(Zrow[0] + v0, Zrow[1] + v1, Zrow[2] + v2, Zrow[3] + v3);
            float u0 = __shfl_sync(0xffffffffu, ur, base + 0);
            float u1 = __shfl_sync(0xffffffffu, ur, base + 1);
            float u2 = __shfl_sync(0xffffffffu, ur, base + 2);
            float u3 = __shfl_sync(0xffffffffu, ur, base + 3);
            vr = -lse4(Zcol[0] + u0, Zcol[1] + u1, Zcol[2] + u2, Zcol[3] + u3);
        }
        float v0 = __shfl_sync(0xffffffffu, vr, base + 0);
        float v1 = __shfl_sync(0xffffffffu, vr, base + 1);
        float v2 = __shfl_sync(0xffffffffu, vr, base + 2);
        float v3 = __shfl_sync(0xffffffffu, vr, base + 3);
        g_Hres[t * 16 + r * 4 + 0] = __expf(Zrow[0] + ur + v0);
        g_Hres[t * 16 + r * 4 + 1] = __expf(Zrow[1] + ur + v1);
        g_Hres[t * 16 + r * 4 + 2] = __expf(Zrow[2] + ur + v2);
        g_Hres[t * 16 + r * 4 + 3] = __expf(Zrow[3] + ur + v3);
    }
    __syncthreads();

    // ---- pass 3: x_layer, bf16 hi/lo split ----
    #pragma unroll 4
    for (int gg = 0; gg < TOKB; gg++) {
        const long t = t0 + gg;
        const float h0 = s_hpre[gg][0], h1 = s_hpre[gg][1];
        const float h2 = s_hpre[gg][2], h3 = s_hpre[gg][3];
        const float4* xr = (const float4*)(x + t * D);
        float4 a = xr[tid], b = xr[256 + tid], c = xr[512 + tid], e = xr[768 + tid];
        float4 o;
        o.x = h0 * a.x + h1 * b.x + h2 * c.x + h3 * e.x;
        o.y = h0 * a.y + h1 * b.y + h2 * c.y + h3 * e.y;
        o.z = h0 * a.z + h1 * b.z + h2 * c.z + h3 * e.z;
        o.w = h0 * a.w + h1 * b.w + h2 * c.w + h3 * e.w;
        float hx = __bfloat162float(__float2bfloat16_rn(o.x));
        float hy = __bfloat162float(__float2bfloat16_rn(o.y));
        float hz = __bfloat162float(__float2bfloat16_rn(o.z));
        float hw = __bfloat162float(__float2bfloat16_rn(o.w));
        uint2 hv, lv;
        hv.x = pack2bf(hx, hy);             hv.y = pack2bf(hz, hw);
        lv.x = pack2bf(o.x - hx, o.y - hy); lv.y = pack2bf(o.z - hz, o.w - hw);
        ((uint2*)g_xhi)[t * 256 + tid] = hv;
        ((uint2*)g_xlo)[t * 256 + tid] = lv;
    }
}

// ============================================================
// Kernel 1b: split W_sub into bf16 hi/lo
// ============================================================
__global__ __launch_bounds__(256)
void wsplit_kernel(const float* __restrict__ W)
{
    int i = blockIdx.x * 256 + threadIdx.x;
    float4 v = ((const float4*)W)[i];
    float hx = __bfloat162float(__float2bfloat16_rn(v.x));
    float hy = __bfloat162float(__float2bfloat16_rn(v.y));
    float hz = __bfloat162float(__float2bfloat16_rn(v.z));
    float hw = __bfloat162float(__float2bfloat16_rn(v.w));
    uint2 hv, lv;
    hv.x = pack2bf(hx, hy);             hv.y = pack2bf(hz, hw);
    lv.x = pack2bf(v.x - hx, v.y - hy); lv.y = pack2bf(v.z - hz, v.w - hw);
    ((uint2*)g_whi)[i] = hv;
    ((uint2*)g_wlo)[i] = lv;
}

// ============================================================
// Kernel 2: bf16-split GEMM via mma.sync (HMMA tensor path)
//   CTA 128x128, 8 warps (32x64 each), GK=64/stage, 3-stage cp.async
// ============================================================
#define GM 128
#define GN 128
#define GK 64
#define ST_AHI 0
#define ST_ALO 16384
#define ST_BHI 32768
#define ST_BLO 49152
#define STAGE_BYTES 65536
#define GEMM_SMEM (3 * STAGE_BYTES)

__device__ __forceinline__ void load_stage(
    uint32_t sstage, int tid, int m0, int n0, int k0,
    const __nv_bfloat16* __restrict__ Ahi, const __nv_bfloat16* __restrict__ Alo,
    const __nv_bfloat16* __restrict__ Bhi, const __nv_bfloat16* __restrict__ Blo)
{
    #pragma unroll
    for (int j = 0; j < 4; j++) {
        int i = tid + (j << 8);          // 0..1023 granules per matrix
        int r = i >> 3, c = i & 7;
        uint32_t so = SW128((uint32_t)(r * 128 + c * 16));
        size_t goA = (size_t)(m0 + r) * HID + k0 + c * 8;
        size_t goB = (size_t)(n0 + r) * HID + k0 + c * 8;
        cp16(sstage + ST_AHI + so, Ahi + goA);
        cp16(sstage + ST_ALO + so, Alo + goA);
        cp16(sstage + ST_BHI + so, Bhi + goB);
        cp16(sstage + ST_BLO + so, Blo + goB);
    }
}

__global__ __launch_bounds__(256, 1)
void gemm_tc_kernel(const __nv_bfloat16* __restrict__ Ahi,
                    const __nv_bfloat16* __restrict__ Alo,
                    const __nv_bfloat16* __restrict__ Bhi,
                    const __nv_bfloat16* __restrict__ Blo,
                    float* __restrict__ Cy)
{
    extern __shared__ char smem[];
    uint32_t sbase = smem_to_u32(smem);
    const int tid = threadIdx.x, wid = tid >> 5, lane = tid & 31;
    const int wm = wid & 3, wn = wid >> 2;        // warp tile: rows 32*wm, cols 64*wn
    const int m0 = blockIdx.y * GM, n0 = blockIdx.x * GN;

    float acc[2][8][4];
    #pragma unroll
    for (int h = 0; h < 2; h++)
        #pragma unroll
        for (int g = 0; g < 8; g++)
            #pragma unroll
            for (int q = 0; q < 4; q++) acc[h][g][q] = 0.f;

    // precomputed ldmatrix lane offsets (within-tile bytes, pre-swizzle inputs)
    const int a_row = (lane & 15);
    const int a_kx  = ((lane >> 4) & 1) * 16;
    const int b_row = (lane & 7) + ((lane >> 4) & 1) * 8;
    const int b_kx  = ((lane >> 3) & 1) * 16;

    load_stage(sbase, tid, m0, n0, 0, Ahi, Alo, Bhi, Blo);
    asm volatile("cp.async.commit_group;" ::: "memory");
    load_stage(sbase + STAGE_BYTES, tid, m0, n0, GK, Ahi, Alo, Bhi, Blo);
    asm volatile("cp.async.commit_group;" ::: "memory");

    const int NITER = HID / GK;   // 16
    for (int i = 0; i < NITER; i++) {
        if (i + 2 < NITER) asm volatile("cp.async.wait_group 1;" ::: "memory");
        else               asm volatile("cp.async.wait_group 0;" ::: "memory");
        __syncthreads();

        if (i + 2 < NITER) {
            load_stage(sbase + ((i + 2) % 3) * STAGE_BYTES, tid, m0, n0, (i + 2) * GK,
                       Ahi, Alo, Bhi, Blo);
            asm volatile("cp.async.commit_group;" ::: "memory");
        }

        uint32_t stg = sbase + (i % 3) * STAGE_BYTES;
        #pragma unroll
        for (int kk = 0; kk < 4; kk++) {
            const int kb = kk * 32;
            uint32_t ah[2][4], al[2][4], bh[4][4], bl[4][4];
            #pragma unroll
            for (int h = 0; h < 2; h++) {
                uint32_t off = SW128((uint32_t)((32 * wm + 16 * h + a_row) * 128 + kb + a_kx));
                ldsm_x4(ah[h][0], ah[h][1], ah[h][2], ah[h][3], stg + ST_AHI + off);
                ldsm_x4(al[h][0], al[h][1], al[h][2], al[h][3], stg + ST_ALO + off);
            }
            #pragma unroll
            for (int g = 0; g < 4; g++) {
                uint32_t off = SW128((uint32_t)((64 * wn + 16 * g + b_row) * 128 + kb + b_kx));
                ldsm_x4(bh[g][0], bh[g][1], bh[g][2], bh[g][3], stg + ST_BHI + off);
                ldsm_x4(bl[g][0], bl[g][1], bl[g][2], bl[g][3], stg + ST_BLO + off);
            }
            #pragma unroll
            for (int h = 0; h < 2; h++)
                #pragma unroll
                for (int g = 0; g < 4; g++)
                    #pragma unroll
                    for (int half = 0; half < 2; half++) {
                        int ng = g * 2 + half;
                        mma16816(acc[h][ng], ah[h], &bh[g][2 * half]);
                        mma16816(acc[h][ng], ah[h], &bl[g][2 * half]);
                        mma16816(acc[h][ng], al[h], &bh[g][2 * half]);
                    }
        }
        __syncthreads();
    }

    // epilogue: c frag lane mapping: row = lane>>2 (+8 for c2/c3), col = (lane&3)*2
    const int er = m0 + 32 * wm + (lane >> 2);
    const int ec = n0 + 64 * wn + (lane & 3) * 2;
    #pragma unroll
    for (int h = 0; h < 2; h++)
        #pragma unroll
        for (int ng = 0; ng < 8; ng++) {
            float* base = Cy + (size_t)(er + 16 * h) * HID + ec + 8 * ng;
            *(float2*)(base)              = make_float2(acc[h][ng][0], acc[h][ng][1]);
            *(float2*)(base + 8 * HID)    = make_float2(acc[h][ng][2], acc[h][ng][3]);
        }
}

// ============================================================
// Kernel 3: residual mix epilogue
// ============================================================
__global__ __launch_bounds__(256)
void mix_kernel(const float* __restrict__ x, float* __restrict__ out)
{
    const long t = blockIdx.x;
    const int tid = threadIdx.x;
    __shared__ float s_h[16];
    __shared__ float s_p[4];
    if (tid < 16) s_h[tid] = g_Hres[t * 16 + tid];
    if (tid < 4)  s_p[tid] = g_Hpost[t * 4 + tid];
    __syncthreads();

    const float4* xr = (const float4*)(x + t * D);
    const float4* yr = (const float4*)(g_y + t * HID);
    float4* op = (float4*)(out + t * D);

    float4 xi0 = xr[tid], xi1 = xr[256 + tid], xi2 = xr[512 + tid], xi3 = xr[768 + tid];
    float4 y4 = yr[tid];

    #pragma unroll
    for (int o = 0; o < 4; o++) {
        float h0 = s_h[o * 4 + 0], h1 = s_h[o * 4 + 1];
        float h2 = s_h[o * 4 + 2], h3 = s_h[o * 4 + 3];
        float p = s_p[o];
        float4 r;
        r.x = h0 * xi0.x + h1 * xi1.x + h2 * xi2.x + h3 * xi3.x + p * y4.x;
        r.y = h0 * xi0.y + h1 * xi1.y + h2 * xi2.y + h3 * xi3.y + p * y4.y;
        r.z = h0 * xi0.z + h1 * xi1.z + h2 * xi2.z + h3 * xi3.z + p * y4.z;
        r.w = h0 * xi0.w + h1 * xi1.w + h2 * xi2.w + h3 * xi3.w + p * y4.w;
        op[o * 256 + tid] = r;
    }
}

// ============================================================
extern "C" void kernel_launch(void* const* d_in, const int* in_sizes, int n_in,
                              void* d_out, int out_size)
{
    const float* x      = (const float*)d_in[0];
    const float* rmsw   = (const float*)d_in[1];
    const float* Wpre   = (const float*)d_in[2];
    const float* Wpost  = (const float*)d_in[3];
    const float* Wres   = (const float*)d_in[4];
    const float* bpre   = (const float*)d_in[5];
    const float* bpost  = (const float*)d_in[6];
    const float* bres   = (const float*)d_in[7];
    const float* apre   = (const float*)d_in[8];
    const float* apost  = (const float*)d_in[9];
    const float* ares   = (const float*)d_in[10];
    const float* Wsub   = (const float*)d_in[11];
    float* out = (float*)d_out;

    __nv_bfloat16 *xhi_p, *xlo_p, *whi_p, *wlo_p;
    float* y_p;
    cudaGetSymbolAddress((void**)&xhi_p, g_xhi);
    cudaGetSymbolAddress((void**)&xlo_p, g_xlo);
    cudaGetSymbolAddress((void**)&whi_p, g_whi);
    cudaGetSymbolAddress((void**)&wlo_p, g_wlo);
    cudaGetSymbolAddress((void**)&y_p, g_y);

    cudaFuncSetAttribute(gemm_tc_kernel,
                         cudaFuncAttributeMaxDynamicSharedMemorySize, GEMM_SMEM);

    gates_kernel<<<T_TOKENS / TOKB, 256>>>(x, rmsw, Wpre, Wpost, Wres,
                                           bpre, bpost, bres, apre, apost, ares);
    wsplit_kernel<<<HID * HID / 4 / 256, 256>>>(Wsub);
    gemm_tc_kernel<<<dim3(HID / GN, T_TOKENS / GM), 256, GEMM_SMEM>>>(
        xhi_p, xlo_p, whi_p, wlo_p, y_p);
    mix_kernel<<<T_TOKENS, 256>>>(x, out);
}

// round 4
// speedup vs baseline: 2.4191x; 1.0486x over previous
#include <cuda_runtime.h>
#include <cuda_bf16.h>
#include <cstdint>
#include <math.h>

#define T_TOKENS 8192
#define D        4096
#define NS       4
#define HID      1024
#define NW       24
#define KT       128
#define TOKB     16
#define TAU_INV  20.0f
#define EPS_W    1e-6f

// ================= scratch =================
__device__ __nv_bfloat16 g_xhi[T_TOKENS * HID];
__device__ __nv_bfloat16 g_xlo[T_TOKENS * HID];
__device__ __nv_bfloat16 g_whi[HID * HID];
__device__ __nv_bfloat16 g_wlo[HID * HID];
__device__ float g_wg[NW * D];                 // W' = W * rmsw, 24 rows
__device__ float g_Hpost[T_TOKENS * NS];
__device__ float g_Hres[T_TOKENS * NS * NS];

// ================= helpers =================
__device__ __forceinline__ uint32_t smem_to_u32(const void* p) {
    uint32_t a;
    asm("{ .reg .u64 t; cvta.to.shared.u64 t, %1; cvt.u32.u64 %0, t; }" : "=r"(a) : "l"(p));
    return a;
}
__device__ __forceinline__ void cp16(uint32_t s, const void* g) {
    asm volatile("cp.async.cg.shared.global [%0], [%1], 16;" :: "r"(s), "l"(g));
}
__device__ __forceinline__ void ldsm_x4(uint32_t& r0, uint32_t& r1, uint32_t& r2,
                                        uint32_t& r3, uint32_t addr) {
    asm volatile("ldmatrix.sync.aligned.m8n8.x4.shared.b16 {%0,%1,%2,%3}, [%4];"
                 : "=r"(r0), "=r"(r1), "=r"(r2), "=r"(r3) : "r"(addr));
}
__device__ __forceinline__ void mma16816(float* c, const uint32_t* a, const uint32_t* b) {
    asm volatile(
        "mma.sync.aligned.m16n8k16.row.col.f32.bf16.bf16.f32 "
        "{%0,%1,%2,%3}, {%4,%5,%6,%7}, {%8,%9}, {%0,%1,%2,%3};"
        : "+f"(c[0]), "+f"(c[1]), "+f"(c[2]), "+f"(c[3])
        : "r"(a[0]), "r"(a[1]), "r"(a[2]), "r"(a[3]), "r"(b[0]), "r"(b[1]));
}
#define SW128(off) ((off) ^ (((off) >> 3) & 0x70))

__device__ __forceinline__ float lse4(float a0, float a1, float a2, float a3) {
    float m = fmaxf(fmaxf(a0, a1), fmaxf(a2, a3));
    float s = __expf(a0 - m) + __expf(a1 - m) + __expf(a2 - m) + __expf(a3 - m);
    return m + __logf(s);
}
__device__ __forceinline__ uint32_t pack2bf(float a, float b) {
    __nv_bfloat162 t = __floats2bfloat162_rn(a, b);
    return *(uint32_t*)&t;
}

// ============================================================
// Kernel 0: fold rms weight into gate weights  W'[m][k] = W[m][k]*rmsw[k]
// ============================================================
__global__ __launch_bounds__(256)
void wprep_kernel(const float* __restrict__ Wpre, const float* __restrict__ Wpost,
                  const float* __restrict__ Wres, const float* __restrict__ rmsw)
{
    int idx = blockIdx.x * 256 + threadIdx.x;    // 0 .. 24*4096-1
    int m = idx >> 12, k = idx & 4095;
    const float* Wr = (m < 4) ? (Wpre + m * D)
                     : (m < 8) ? (Wpost + (m - 4) * D)
                               : (Wres + (m - 8) * D);
    g_wg[idx] = Wr[k] * rmsw[k];
}

// ============================================================
// Kernel 1b: split W_sub into bf16 hi/lo
// ============================================================
__global__ __launch_bounds__(256)
void wsplit_kernel(const float* __restrict__ W)
{
    int i = blockIdx.x * 256 + threadIdx.x;
    float4 v = ((const float4*)W)[i];
    float hx = __bfloat162float(__float2bfloat16_rn(v.x));
    float hy = __bfloat162float(__float2bfloat16_rn(v.y));
    float hz = __bfloat162float(__float2bfloat16_rn(v.z));
    float hw = __bfloat162float(__float2bfloat16_rn(v.w));
    uint2 hv, lv;
    hv.x = pack2bf(hx, hy);             hv.y = pack2bf(hz, hw);
    lv.x = pack2bf(v.x - hx, v.y - hy); lv.y = pack2bf(v.z - hz, v.w - hw);
    ((uint2*)g_whi)[i] = hv;
    ((uint2*)g_wlo)[i] = lv;
}

// ============================================================
// Kernel 1: gates + sinkhorn + x_layer (bf16 hi/lo out)
//   16 tokens/block, 256 threads, 3-stage cp.async pipeline.
// smem layout (bytes):
//   stage s (s=0..2) at s*20864:  W tile [24][132]f (12672B), x tile [16][128]f (8192B)
//   62592: s_dots [16][24]f   64128: s_inv[16]   64192: s_hpre[16][4]
// ============================================================
#define G_STAGE    20864
#define G_XOFF     12672
#define GATES_SMEM 64448

__device__ __forceinline__ void gates_load_stage(
    uint32_t sst, int tid, const float* __restrict__ wg,
    const float* __restrict__ x, long t0, int k0)
{
    #pragma unroll
    for (int j = 0; j < 3; j++) {
        int idx = tid + j * 256;           // 0..767  (24 rows x 32 chunks)
        int m = idx >> 5, c = idx & 31;
        cp16(sst + m * 528 + c * 16, wg + m * D + k0 + c * 4);
    }
    #pragma unroll
    for (int j = 0; j < 2; j++) {
        int idx = tid + j * 256;           // 0..511  (16 tokens x 32 chunks)
        int tok = idx >> 5, c = idx & 31;
        cp16(sst + G_XOFF + tok * 512 + c * 16, x + (t0 + tok) * (long)D + k0 + c * 4);
    }
}

__global__ __launch_bounds__(256, 3)
void gates_kernel(const float* __restrict__ x,
                  const float* __restrict__ bpre,
                  const float* __restrict__ bpost,
                  const float* __restrict__ bres,
                  const float* __restrict__ apre,
                  const float* __restrict__ apost,
                  const float* __restrict__ ares)
{
    extern __shared__ __align__(16) char gsm[];
    const uint32_t sbase = smem_to_u32(gsm);
    float* s_dots = (float*)(gsm + 62592);   // [16][24]
    float* s_inv  = (float*)(gsm + 64128);   // [16]
    float* s_hpre = (float*)(gsm + 64192);   // [16][4]

    const int tid  = threadIdx.x;
    const int lane = tid & 31;
    const long t0  = (long)blockIdx.x * TOKB;

    const int ks = tid & 3;            // k quarter
    const int mt = (tid >> 2) & 7;     // m triple
    const int tp = tid >> 5;           // token pair (2tp, 2tp+1)

    float acc[2][3] = {{0.f,0.f,0.f},{0.f,0.f,0.f}};
    float ss0 = 0.f, ss1 = 0.f;

    const float* wg = g_wg;

    gates_load_stage(sbase, tid, wg, x, t0, 0);
    asm volatile("cp.async.commit_group;" ::: "memory");
    gates_load_stage(sbase + G_STAGE, tid, wg, x, t0, KT);
    asm volatile("cp.async.commit_group;" ::: "memory");

    const int NIT = D / KT;            // 32
    for (int kt = 0; kt < NIT; kt++) {
        const int s = kt % 3;
        if (kt < NIT - 1) asm volatile("cp.async.wait_group 1;" ::: "memory");
        else              asm volatile("cp.async.wait_group 0;" ::: "memory");
        __syncthreads();
        if (kt + 2 < NIT) {
            gates_load_stage(sbase + ((kt + 2) % 3) * G_STAGE, tid, wg, x, t0,
                             (kt + 2) * KT);
            asm volatile("cp.async.commit_group;" ::: "memory");
        }

        const float4* sw  = (const float4*)(gsm + s * G_STAGE);
        const float4* x4a = (const float4*)(gsm + s * G_STAGE + G_XOFF) + (2 * tp) * 32;
        const float4* x4b = x4a + 32;
        #pragma unroll
        for (int kk = 0; kk < 8; kk++) {
            int k4 = ks * 8 + ((kk + 2 * ks) & 7);
            float4 xa = x4a[k4];
            float4 xb = x4b[k4];
            ss0 = fmaf(xa.x, xa.x, fmaf(xa.y, xa.y, fmaf(xa.z, xa.z, fmaf(xa.w, xa.w, ss0))));
            ss1 = fmaf(xb.x, xb.x, fmaf(xb.y, xb.y, fmaf(xb.z, xb.z, fmaf(xb.w, xb.w, ss1))));
            #pragma unroll
            for (int j = 0; j < 3; j++) {
                float4 w = sw[(3 * mt + j) * 33 + k4];
                acc[0][j] = fmaf(xa.x, w.x, fmaf(xa.y, w.y, fmaf(xa.z, w.z, fmaf(xa.w, w.w, acc[0][j]))));
                acc[1][j] = fmaf(xb.x, w.x, fmaf(xb.y, w.y, fmaf(xb.z, w.z, fmaf(xb.w, w.w, acc[1][j]))));
            }
        }
    }

    // sumsq: each k counted 8x across mt lanes -> /8 after full-warp reduce
    #pragma unroll
    for (int o = 16; o; o >>= 1) {
        ss0 += __shfl_xor_sync(0xffffffffu, ss0, o);
        ss1 += __shfl_xor_sync(0xffffffffu, ss1, o);
    }
    // k-split reduce over ks bits
    #pragma unroll
    for (int i = 0; i < 2; i++)
        #pragma unroll
        for (int j = 0; j < 3; j++) {
            float a = acc[i][j];
            a += __shfl_xor_sync(0xffffffffu, a, 1);
            a += __shfl_xor_sync(0xffffffffu, a, 2);
            acc[i][j] = a;
        }
    __syncthreads();
    if (lane == 0) {
        float i0 = rsqrtf(ss0 * (0.125f / D) + 1e-8f);
        float i1 = rsqrtf(ss1 * (0.125f / D) + 1e-8f);
        s_inv[2 * tp]     = i0;
        s_inv[2 * tp + 1] = i1;
    }
    if (ks == 0) {
        #pragma unroll
        for (int i = 0; i < 2; i++)
            #pragma unroll
            for (int j = 0; j < 3; j++)
                s_dots[(2 * tp + i) * NW + 3 * mt + j] = acc[i][j];
    }
    __syncthreads();

    // ---- gate math: 2 warps, 4 lanes per token ----
    if (tid < 64) {
        const int w2 = tid >> 5;
        const int tt = w2 * 8 + (lane >> 2), r = lane & 3;
        const int base = lane & ~3;
        const long t = t0 + tt;
        const float inv = s_inv[tt];
        const float* dt = s_dots + tt * NW;
        const float a_pre = apre[0], a_post = apost[0], a_res = ares[0];

        float zp = fmaf(a_pre, inv * dt[r], bpre[r]);
        float hp = 1.0f / (1.0f + __expf(-zp));
        float sp = hp;
        sp += __shfl_xor_sync(0xffffffffu, sp, 1);
        sp += __shfl_xor_sync(0xffffffffu, sp, 2);
        s_hpre[tt * 4 + r] = hp / (sp + EPS_W);

        float zq = fmaf(a_post, inv * dt[4 + r], bpost[r]);
        float hq = 2.0f / (1.0f + __expf(-zq));
        float sq = hq;
        sq += __shfl_xor_sync(0xffffffffu, sq, 1);
        sq += __shfl_xor_sync(0xffffffffu, sq, 2);
        g_Hpost[t * NS + r] = hq / (sq + EPS_W);

        float Zrow[4], Zcol[4];
        #pragma unroll
        for (int i = 0; i < 4; i++) {
            Zrow[i] = fmaf(a_res, inv * dt[8 + r * 4 + i], bres[r * 4 + i]) * TAU_INV;
            Zcol[i] = fmaf(a_res, inv * dt[8 + i * 4 + r], bres[i * 4 + r]) * TAU_INV;
        }
        float ur = 0.f, vr = 0.f;
        for (int it = 0; it < 20; it++) {
            float v0 = __shfl_sync(0xffffffffu, vr, base + 0);
            float v1 = __shfl_sync(0xffffffffu, vr, base + 1);
            float v2 = __shfl_sync(0xffffffffu, vr, base + 2);
            float v3 = __shfl_sync(0xffffffffu, vr, base + 3);
            ur = -lse4(Zrow[0] + v0, Zrow[1] + v1, Zrow[2] + v2, Zrow[3] + v3);
            float u0 = __shfl_sync(0xffffffffu, ur, base + 0);
            float u1 = __shfl_sync(0xffffffffu, ur, base + 1);
            float u2 = __shfl_sync(0xffffffffu, ur, base + 2);
            float u3 = __shfl_sync(0xffffffffu, ur, base + 3);
            vr = -lse4(Zcol[0] + u0, Zcol[1] + u1, Zcol[2] + u2, Zcol[3] + u3);
        }
        float v0 = __shfl_sync(0xffffffffu, vr, base + 0);
        float v1 = __shfl_sync(0xffffffffu, vr, base + 1);
        float v2 = __shfl_sync(0xffffffffu, vr, base + 2);
        float v3 = __shfl_sync(0xffffffffu, vr, base + 3);
        g_Hres[t * 16 + r * 4 + 0] = __expf(Zrow[0] + ur + v0);
        g_Hres[t * 16 + r * 4 + 1] = __expf(Zrow[1] + ur + v1);
        g_Hres[t * 16 + r * 4 + 2] = __expf(Zrow[2] + ur + v2);
        g_Hres[t * 16 + r * 4 + 3] = __expf(Zrow[3] + ur + v3);
    }
    __syncthreads();

    // ---- pass 3: x_layer, bf16 hi/lo split ----
    #pragma unroll 4
    for (int gg = 0; gg < TOKB; gg++) {
        const long t = t0 + gg;
        const float h0 = s_hpre[gg * 4 + 0], h1 = s_hpre[gg * 4 + 1];
        const float h2 = s_hpre[gg * 4 + 2], h3 = s_hpre[gg * 4 + 3];
        const float4* xr = (const float4*)(x + t * D);
        float4 a = xr[tid], b = xr[256 + tid], c = xr[512 + tid], e = xr[768 + tid];
        float4 o;
        o.x = h0 * a.x + h1 * b.x + h2 * c.x + h3 * e.x;
        o.y = h0 * a.y + h1 * b.y + h2 * c.y + h3 * e.y;
        o.z = h0 * a.z + h1 * b.z + h2 * c.z + h3 * e.z;
        o.w = h0 * a.w + h1 * b.w + h2 * c.w + h3 * e.w;
        float hx = __bfloat162float(__float2bfloat16_rn(o.x));
        float hy = __bfloat162float(__float2bfloat16_rn(o.y));
        float hz = __bfloat162float(__float2bfloat16_rn(o.z));
        float hw = __bfloat162float(__float2bfloat16_rn(o.w));
        uint2 hv, lv;
        hv.x = pack2bf(hx, hy);             hv.y = pack2bf(hz, hw);
        lv.x = pack2bf(o.x - hx, o.y - hy); lv.y = pack2bf(o.z - hz, o.w - hw);
        ((uint2*)g_xhi)[t * 256 + tid] = hv;
        ((uint2*)g_xlo)[t * 256 + tid] = lv;
    }
}

// ============================================================
// Kernel 2: bf16-split GEMM (mma.sync) + FUSED residual-mix epilogue
//   CTA 128x128, 8 warps, GK=64/stage, 3-stage cp.async, 1 sync/iter.
//   Epilogue: y tile -> smem, then coalesced mix writes d_out directly.
// ============================================================
#define GM 128
#define GN 128
#define GK 64
#define ST_AHI 0
#define ST_ALO 16384
#define ST_BHI 32768
#define ST_BLO 49152
#define STAGE_BYTES 65536
#define GEMM_SMEM (3 * STAGE_BYTES)
// epilogue reuse: y_s [128][132]f at 0 (67584B), sHres [128][16]f at 69632,
// sHpost [128][4]f at 77824
#define EP_YS   0
#define EP_HRES 69632
#define EP_HPST 77824

__device__ __forceinline__ void load_stage(
    uint32_t sstage, int tid, int m0, int n0, int k0,
    const __nv_bfloat16* __restrict__ Ahi, const __nv_bfloat16* __restrict__ Alo,
    const __nv_bfloat16* __restrict__ Bhi, const __nv_bfloat16* __restrict__ Blo)
{
    #pragma unroll
    for (int j = 0; j < 4; j++) {
        int i = tid + (j << 8);
        int r = i >> 3, c = i & 7;
        uint32_t so = SW128((uint32_t)(r * 128 + c * 16));
        size_t goA = (size_t)(m0 + r) * HID + k0 + c * 8;
        size_t goB = (size_t)(n0 + r) * HID + k0 + c * 8;
        cp16(sstage + ST_AHI + so, Ahi + goA);
        cp16(sstage + ST_ALO + so, Alo + goA);
        cp16(sstage + ST_BHI + so, Bhi + goB);
        cp16(sstage + ST_BLO + so, Blo + goB);
    }
}

__global__ __launch_bounds__(256, 1)
void gemm_tc_kernel(const __nv_bfloat16* __restrict__ Ahi,
                    const __nv_bfloat16* __restrict__ Alo,
                    const __nv_bfloat16* __restrict__ Bhi,
                    const __nv_bfloat16* __restrict__ Blo,
                    const float* __restrict__ x,
                    float* __restrict__ out)
{
    extern __shared__ __align__(16) char smem[];
    uint32_t sbase = smem_to_u32(smem);
    const int tid = threadIdx.x, wid = tid >> 5, lane = tid & 31;
    const int wm = wid & 3, wn = wid >> 2;
    const int m0 = blockIdx.y * GM, n0 = blockIdx.x * GN;

    float acc[2][8][4];
    #pragma unroll
    for (int h = 0; h < 2; h++)
        #pragma unroll
        for (int g = 0; g < 8; g++)
            #pragma unroll
            for (int q = 0; q < 4; q++) acc[h][g][q] = 0.f;

    const int a_row = (lane & 15);
    const int a_kx  = ((lane >> 4) & 1) * 16;
    const int b_row = (lane & 7) + ((lane >> 4) & 1) * 8;
    const int b_kx  = ((lane >> 3) & 1) * 16;

    load_stage(sbase, tid, m0, n0, 0, Ahi, Alo, Bhi, Blo);
    asm volatile("cp.async.commit_group;" ::: "memory");
    load_stage(sbase + STAGE_BYTES, tid, m0, n0, GK, Ahi, Alo, Bhi, Blo);
    asm volatile("cp.async.commit_group;" ::: "memory");

    const int NITER = HID / GK;   // 16
    for (int i = 0; i < NITER; i++) {
        if (i < NITER - 1) asm volatile("cp.async.wait_group 1;" ::: "memory");
        else               asm volatile("cp.async.wait_group 0;" ::: "memory");
        __syncthreads();
        if (i + 2 < NITER) {
            load_stage(sbase + ((i + 2) % 3) * STAGE_BYTES, tid, m0, n0, (i + 2) * GK,
                       Ahi, Alo, Bhi, Blo);
            asm volatile("cp.async.commit_group;" ::: "memory");
        }

        uint32_t stg = sbase + (i % 3) * STAGE_BYTES;
        #pragma unroll
        for (int kk = 0; kk < 4; kk++) {
            const int kb = kk * 32;
            uint32_t ah[2][4], al[2][4], bh[4][4], bl[4][4];
            #pragma unroll
            for (int h = 0; h < 2; h++) {
                uint32_t off = SW128((uint32_t)((32 * wm + 16 * h + a_row) * 128 + kb + a_kx));
                ldsm_x4(ah[h][0], ah[h][1], ah[h][2], ah[h][3], stg + ST_AHI + off);
                ldsm_x4(al[h][0], al[h][1], al[h][2], al[h][3], stg + ST_ALO + off);
            }
            #pragma unroll
            for (int g = 0; g < 4; g++) {
                uint32_t off = SW128((uint32_t)((64 * wn + 16 * g + b_row) * 128 + kb + b_kx));
                ldsm_x4(bh[g][0], bh[g][1], bh[g][2], bh[g][3], stg + ST_BHI + off);
                ldsm_x4(bl[g][0], bl[g][1], bl[g][2], bl[g][3], stg + ST_BLO + off);
            }
            #pragma unroll
            for (int h = 0; h < 2; h++)
                #pragma unroll
                for (int g = 0; g < 4; g++)
                    #pragma unroll
                    for (int half = 0; half < 2; half++) {
                        int ng = g * 2 + half;
                        mma16816(acc[h][ng], ah[h], &bh[g][2 * half]);
                        mma16816(acc[h][ng], ah[h], &bl[g][2 * half]);
                        mma16816(acc[h][ng], al[h], &bh[g][2 * half]);
                    }
        }
    }

    // ================== fused mix epilogue ==================
    __syncthreads();                       // everyone done with pipeline smem
    float* ys  = (float*)(smem + EP_YS);   // [128][132]
    float* shr = (float*)(smem + EP_HRES); // [128][16]
    float* shp = (float*)(smem + EP_HPST); // [128][4]

    // stage y fragments to smem
    {
        const int r0 = 32 * wm + (lane >> 2);
        const int c0 = 64 * wn + (lane & 3) * 2;
        #pragma unroll
        for (int h = 0; h < 2; h++)
            #pragma unroll
            for (int ng = 0; ng < 8; ng++) {
                int rr = r0 + 16 * h, cc = c0 + 8 * ng;
                *(float2*)&ys[rr * 132 + cc]       = make_float2(acc[h][ng][0], acc[h][ng][1]);
                *(float2*)&ys[(rr + 8) * 132 + cc] = make_float2(acc[h][ng][2], acc[h][ng][3]);
            }
    }
    // load gate coefficients for this token block
    #pragma unroll
    for (int j = 0; j < 8; j++) shr[tid + j * 256] = g_Hres[(size_t)m0 * 16 + tid + j * 256];
    #pragma unroll
    for (int j = 0; j < 2; j++) shp[tid + j * 256] = g_Hpost[(size_t)m0 * 4 + tid + j * 256];
    __syncthreads();

    // coalesced mix: warp lanes sweep columns, 8 token-rows per warp-iter
    const int col4 = lane;                 // 0..31 -> 4 floats each (128 cols)
    #pragma unroll 2
    for (int it = 0; it < 16; it++) {
        const int trow = wid + 8 * it;
        const size_t t = (size_t)(m0 + trow);
        const float* hr = shr + trow * 16;
        const float p0 = shp[trow * 4 + 0], p1 = shp[trow * 4 + 1];
        const float p2 = shp[trow * 4 + 2], p3 = shp[trow * 4 + 3];
        float4 y4 = *(const float4*)&ys[trow * 132 + col4 * 4];
        const float* xb = x + t * D + n0 + col4 * 4;
        float4 xi0 = *(const float4*)(xb);
        float4 xi1 = *(const float4*)(xb + 1024);
        float4 xi2 = *(const float4*)(xb + 2048);
        float4 xi3 = *(const float4*)(xb + 3072);
        float* ob = out + t * D + n0 + col4 * 4;
        #pragma unroll
        for (int o = 0; o < 4; o++) {
            const float h0 = hr[o * 4 + 0], h1 = hr[o * 4 + 1];
            const float h2 = hr[o * 4 + 2], h3 = hr[o * 4 + 3];
            const float p = (o == 0) ? p0 : (o == 1) ? p1 : (o == 2) ? p2 : p3;
            float4 r;
            r.x = h0 * xi0.x + h1 * xi1.x + h2 * xi2.x + h3 * xi3.x + p * y4.x;
            r.y = h0 * xi0.y + h1 * xi1.y + h2 * xi2.y + h3 * xi3.y + p * y4.y;
            r.z = h0 * xi0.z + h1 * xi1.z + h2 * xi2.z + h3 * xi3.z + p * y4.z;
            r.w = h0 * xi0.w + h1 * xi1.w + h2 * xi2.w + h3 * xi3.w + p * y4.w;
            *(float4*)(ob + o * 1024) = r;
        }
    }
}

// ============================================================
extern "C" void kernel_launch(void* const* d_in, const int* in_sizes, int n_in,
                              void* d_out, int out_size)
{
    const float* x      = (const float*)d_in[0];
    const float* rmsw   = (const float*)d_in[1];
    const float* Wpre   = (const float*)d_in[2];
    const float* Wpost  = (const float*)d_in[3];
    const float* Wres   = (const float*)d_in[4];
    const float* bpre   = (const float*)d_in[5];
    const float* bpost  = (const float*)d_in[6];
    const float* bres   = (const float*)d_in[7];
    const float* apre   = (const float*)d_in[8];
    const float* apost  = (const float*)d_in[9];
    const float* ares   = (const float*)d_in[10];
    const float* Wsub   = (const float*)d_in[11];
    float* out = (float*)d_out;

    __nv_bfloat16 *xhi_p, *xlo_p, *whi_p, *wlo_p;
    cudaGetSymbolAddress((void**)&xhi_p, g_xhi);
    cudaGetSymbolAddress((void**)&xlo_p, g_xlo);
    cudaGetSymbolAddress((void**)&whi_p, g_whi);
    cudaGetSymbolAddress((void**)&wlo_p, g_wlo);

    cudaFuncSetAttribute(gemm_tc_kernel,
                         cudaFuncAttributeMaxDynamicSharedMemorySize, GEMM_SMEM);
    cudaFuncSetAttribute(gates_kernel,
                         cudaFuncAttributeMaxDynamicSharedMemorySize, GATES_SMEM);

    wprep_kernel<<<NW * D / 256, 256>>>(Wpre, Wpost, Wres, rmsw);
    wsplit_kernel<<<HID * HID / 4 / 256, 256>>>(Wsub);
    gates_kernel<<<T_TOKENS / TOKB, 256, GATES_SMEM>>>(x, bpre, bpost, bres,
                                                       apre, apost, ares);
    gemm_tc_kernel<<<dim3(HID / GN, T_TOKENS / GM), 256, GEMM_SMEM>>>(
        xhi_p, xlo_p, whi_p, wlo_p, x, out);
}

// round 5
// speedup vs baseline: 2.6314x; 1.0877x over previous
#include <cuda_runtime.h>
#include <cuda_bf16.h>
#include <cstdint>
#include <math.h>

#define T_TOKENS 8192
#define D        4096
#define NS       4
#define HID      1024
#define NW       24
#define KT       128
#define TOKB     16
#define TAU_INV  20.0f
#define EPS_W    1e-6f

// ================= scratch =================
__device__ __nv_bfloat16 g_xhi[T_TOKENS * HID];
__device__ __nv_bfloat16 g_xlo[T_TOKENS * HID];
__device__ __nv_bfloat16 g_whi[HID * HID];
__device__ __nv_bfloat16 g_wlo[HID * HID];
__device__ float g_wg[NW * D];                 // W' = W * rmsw, 24 rows
__device__ float g_Hpost[T_TOKENS * NS];
__device__ float g_Hres[T_TOKENS * NS * NS];

// ================= helpers =================
__device__ __forceinline__ uint32_t smem_to_u32(const void* p) {
    uint32_t a;
    asm("{ .reg .u64 t; cvta.to.shared.u64 t, %1; cvt.u32.u64 %0, t; }" : "=r"(a) : "l"(p));
    return a;
}
__device__ __forceinline__ void cp16(uint32_t s, const void* g) {
    asm volatile("cp.async.cg.shared.global [%0], [%1], 16;" :: "r"(s), "l"(g));
}
__device__ __forceinline__ void ldsm_x4(uint32_t& r0, uint32_t& r1, uint32_t& r2,
                                        uint32_t& r3, uint32_t addr) {
    asm volatile("ldmatrix.sync.aligned.m8n8.x4.shared.b16 {%0,%1,%2,%3}, [%4];"
                 : "=r"(r0), "=r"(r1), "=r"(r2), "=r"(r3) : "r"(addr));
}
__device__ __forceinline__ void mma16816(float* c, const uint32_t* a, const uint32_t* b) {
    asm volatile(
        "mma.sync.aligned.m16n8k16.row.col.f32.bf16.bf16.f32 "
        "{%0,%1,%2,%3}, {%4,%5,%6,%7}, {%8,%9}, {%0,%1,%2,%3};"
        : "+f"(c[0]), "+f"(c[1]), "+f"(c[2]), "+f"(c[3])
        : "r"(a[0]), "r"(a[1]), "r"(a[2]), "r"(a[3]), "r"(b[0]), "r"(b[1]));
}
#define SW64(off) ((off) ^ (((off) >> 3) & 0x30))

__device__ __forceinline__ float lse4(float a0, float a1, float a2, float a3) {
    float m = fmaxf(fmaxf(a0, a1), fmaxf(a2, a3));
    float s = __expf(a0 - m) + __expf(a1 - m) + __expf(a2 - m) + __expf(a3 - m);
    return m + __logf(s);
}
__device__ __forceinline__ uint32_t pack2bf(float a, float b) {
    __nv_bfloat162 t = __floats2bfloat162_rn(a, b);
    return *(uint32_t*)&t;
}

// ============================================================
// Kernel 0: fold rms weight into gate weights
// ============================================================
__global__ __launch_bounds__(256)
void wprep_kernel(const float* __restrict__ Wpre, const float* __restrict__ Wpost,
                  const float* __restrict__ Wres, const float* __restrict__ rmsw)
{
    int idx = blockIdx.x * 256 + threadIdx.x;
    int m = idx >> 12, k = idx & 4095;
    const float* Wr = (m < 4) ? (Wpre + m * D)
                     : (m < 8) ? (Wpost + (m - 4) * D)
                               : (Wres + (m - 8) * D);
    g_wg[idx] = Wr[k] * rmsw[k];
}

// ============================================================
// Kernel 1b: split W_sub into bf16 hi/lo
// ============================================================
__global__ __launch_bounds__(256)
void wsplit_kernel(const float* __restrict__ W)
{
    int i = blockIdx.x * 256 + threadIdx.x;
    float4 v = ((const float4*)W)[i];
    float hx = __bfloat162float(__float2bfloat16_rn(v.x));
    float hy = __bfloat162float(__float2bfloat16_rn(v.y));
    float hz = __bfloat162float(__float2bfloat16_rn(v.z));
    float hw = __bfloat162float(__float2bfloat16_rn(v.w));
    uint2 hv, lv;
    hv.x = pack2bf(hx, hy);             hv.y = pack2bf(hz, hw);
    lv.x = pack2bf(v.x - hx, v.y - hy); lv.y = pack2bf(v.z - hz, v.w - hw);
    ((uint2*)g_whi)[i] = hv;
    ((uint2*)g_wlo)[i] = lv;
}

// ============================================================
// Kernel 1: gates + sinkhorn + x_layer (bf16 hi/lo out)
// ============================================================
#define G_STAGE    20864
#define G_XOFF     12672
#define GATES_SMEM 64448

__device__ __forceinline__ void gates_load_stage(
    uint32_t sst, int tid, const float* __restrict__ wg,
    const float* __restrict__ x, long t0, int k0)
{
    #pragma unroll
    for (int j = 0; j < 3; j++) {
        int idx = tid + j * 256;
        int m = idx >> 5, c = idx & 31;
        cp16(sst + m * 528 + c * 16, wg + m * D + k0 + c * 4);
    }
    #pragma unroll
    for (int j = 0; j < 2; j++) {
        int idx = tid + j * 256;
        int tok = idx >> 5, c = idx & 31;
        cp16(sst + G_XOFF + tok * 512 + c * 16, x + (t0 + tok) * (long)D + k0 + c * 4);
    }
}

__global__ __launch_bounds__(256, 3)
void gates_kernel(const float* __restrict__ x,
                  const float* __restrict__ bpre,
                  const float* __restrict__ bpost,
                  const float* __restrict__ bres,
                  const float* __restrict__ apre,
                  const float* __restrict__ apost,
                  const float* __restrict__ ares)
{
    extern __shared__ __align__(16) char gsm[];
    const uint32_t sbase = smem_to_u32(gsm);
    float* s_dots = (float*)(gsm + 62592);
    float* s_inv  = (float*)(gsm + 64128);
    float* s_hpre = (float*)(gsm + 64192);

    const int tid  = threadIdx.x;
    const int lane = tid & 31;
    const long t0  = (long)blockIdx.x * TOKB;

    const int ks = tid & 3;
    const int mt = (tid >> 2) & 7;
    const int tp = tid >> 5;

    float acc[2][3] = {{0.f,0.f,0.f},{0.f,0.f,0.f}};
    float ss0 = 0.f, ss1 = 0.f;

    const float* wg = g_wg;

    gates_load_stage(sbase, tid, wg, x, t0, 0);
    asm volatile("cp.async.commit_group;" ::: "memory");
    gates_load_stage(sbase + G_STAGE, tid, wg, x, t0, KT);
    asm volatile("cp.async.commit_group;" ::: "memory");

    const int NIT = D / KT;
    for (int kt = 0; kt < NIT; kt++) {
        const int s = kt % 3;
        if (kt < NIT - 1) asm volatile("cp.async.wait_group 1;" ::: "memory");
        else              asm volatile("cp.async.wait_group 0;" ::: "memory");
        __syncthreads();
        if (kt + 2 < NIT) {
            gates_load_stage(sbase + ((kt + 2) % 3) * G_STAGE, tid, wg, x, t0,
                             (kt + 2) * KT);
            asm volatile("cp.async.commit_group;" ::: "memory");
        }

        const float4* sw  = (const float4*)(gsm + s * G_STAGE);
        const float4* x4a = (const float4*)(gsm + s * G_STAGE + G_XOFF) + (2 * tp) * 32;
        const float4* x4b = x4a + 32;
        #pragma unroll
        for (int kk = 0; kk < 8; kk++) {
            int k4 = ks * 8 + ((kk + 2 * ks) & 7);
            float4 xa = x4a[k4];
            float4 xb = x4b[k4];
            ss0 = fmaf(xa.x, xa.x, fmaf(xa.y, xa.y, fmaf(xa.z, xa.z, fmaf(xa.w, xa.w, ss0))));
            ss1 = fmaf(xb.x, xb.x, fmaf(xb.y, xb.y, fmaf(xb.z, xb.z, fmaf(xb.w, xb.w, ss1))));
            #pragma unroll
            for (int j = 0; j < 3; j++) {
                float4 w = sw[(3 * mt + j) * 33 + k4];
                acc[0][j] = fmaf(xa.x, w.x, fmaf(xa.y, w.y, fmaf(xa.z, w.z, fmaf(xa.w, w.w, acc[0][j]))));
                acc[1][j] = fmaf(xb.x, w.x, fmaf(xb.y, w.y, fmaf(xb.z, w.z, fmaf(xb.w, w.w, acc[1][j]))));
            }
        }
    }

    #pragma unroll
    for (int o = 16; o; o >>= 1) {
        ss0 += __shfl_xor_sync(0xffffffffu, ss0, o);
        ss1 += __shfl_xor_sync(0xffffffffu, ss1, o);
    }
    #pragma unroll
    for (int i = 0; i < 2; i++)
        #pragma unroll
        for (int j = 0; j < 3; j++) {
            float a = acc[i][j];
            a += __shfl_xor_sync(0xffffffffu, a, 1);
            a += __shfl_xor_sync(0xffffffffu, a, 2);
            acc[i][j] = a;
        }
    __syncthreads();
    if (lane == 0) {
        s_inv[2 * tp]     = rsqrtf(ss0 * (0.125f / D) + 1e-8f);
        s_inv[2 * tp + 1] = rsqrtf(ss1 * (0.125f / D) + 1e-8f);
    }
    if (ks == 0) {
        #pragma unroll
        for (int i = 0; i < 2; i++)
            #pragma unroll
            for (int j = 0; j < 3; j++)
                s_dots[(2 * tp + i) * NW + 3 * mt + j] = acc[i][j];
    }
    __syncthreads();

    if (tid < 64) {
        const int w2 = tid >> 5;
        const int tt = w2 * 8 + (lane >> 2), r = lane & 3;
        const int base = lane & ~3;
        const long t = t0 + tt;
        const float inv = s_inv[tt];
        const float* dt = s_dots + tt * NW;
        const float a_pre = apre[0], a_post = apost[0], a_res = ares[0];

        float zp = fmaf(a_pre, inv * dt[r], bpre[r]);
        float hp = 1.0f / (1.0f + __expf(-zp));
        float sp = hp;
        sp += __shfl_xor_sync(0xffffffffu, sp, 1);
        sp += __shfl_xor_sync(0xffffffffu, sp, 2);
        s_hpre[tt * 4 + r] = hp / (sp + EPS_W);

        float zq = fmaf(a_post, inv * dt[4 + r], bpost[r]);
        float hq = 2.0f / (1.0f + __expf(-zq));
        float sq = hq;
        sq += __shfl_xor_sync(0xffffffffu, sq, 1);
        sq += __shfl_xor_sync(0xffffffffu, sq, 2);
        g_Hpost[t * NS + r] = hq / (sq + EPS_W);

        float Zrow[4], Zcol[4];
        #pragma unroll
        for (int i = 0; i < 4; i++) {
            Zrow[i] = fmaf(a_res, inv * dt[8 + r * 4 + i], bres[r * 4 + i]) * TAU_INV;
            Zcol[i] = fmaf(a_res, inv * dt[8 + i * 4 + r], bres[i * 4 + r]) * TAU_INV;
        }
        float ur = 0.f, vr = 0.f;
        for (int it = 0; it < 20; it++) {
            float v0 = __shfl_sync(0xffffffffu, vr, base + 0);
            float v1 = __shfl_sync(0xffffffffu, vr, base + 1);
            float v2 = __shfl_sync(0xffffffffu, vr, base + 2);
            float v3 = __shfl_sync(0xffffffffu, vr, base + 3);
            ur = -lse4(Zrow[0] + v0, Zrow[1] + v1, Zrow[2] + v2, Zrow[3] + v3);
            float u0 = __shfl_sync(0xffffffffu, ur, base + 0);
            float u1 = __shfl_sync(0xffffffffu, ur, base + 1);
            float u2 = __shfl_sync(0xffffffffu, ur, base + 2);
            float u3 = __shfl_sync(0xffffffffu, ur, base + 3);
            vr = -lse4(Zcol[0] + u0, Zcol[1] + u1, Zcol[2] + u2, Zcol[3] + u3);
        }
        float v0 = __shfl_sync(0xffffffffu, vr, base + 0);
        float v1 = __shfl_sync(0xffffffffu, vr, base + 1);
        float v2 = __shfl_sync(0xffffffffu, vr, base + 2);
        float v3 = __shfl_sync(0xffffffffu, vr, base + 3);
        g_Hres[t * 16 + r * 4 + 0] = __expf(Zrow[0] + ur + v0);
        g_Hres[t * 16 + r * 4 + 1] = __expf(Zrow[1] + ur + v1);
        g_Hres[t * 16 + r * 4 + 2] = __expf(Zrow[2] + ur + v2);
        g_Hres[t * 16 + r * 4 + 3] = __expf(Zrow[3] + ur + v3);
    }
    __syncthreads();

    #pragma unroll 4
    for (int gg = 0; gg < TOKB; gg++) {
        const long t = t0 + gg;
        const float h0 = s_hpre[gg * 4 + 0], h1 = s_hpre[gg * 4 + 1];
        const float h2 = s_hpre[gg * 4 + 2], h3 = s_hpre[gg * 4 + 3];
        const float4* xr = (const float4*)(x + t * D);
        float4 a = xr[tid], b = xr[256 + tid], c = xr[512 + tid], e = xr[768 + tid];
        float4 o;
        o.x = h0 * a.x + h1 * b.x + h2 * c.x + h3 * e.x;
        o.y = h0 * a.y + h1 * b.y + h2 * c.y + h3 * e.y;
        o.z = h0 * a.z + h1 * b.z + h2 * c.z + h3 * e.z;
        o.w = h0 * a.w + h1 * b.w + h2 * c.w + h3 * e.w;
        float hx = __bfloat162float(__float2bfloat16_rn(o.x));
        float hy = __bfloat162float(__float2bfloat16_rn(o.y));
        float hz = __bfloat162float(__float2bfloat16_rn(o.z));
        float hw = __bfloat162float(__float2bfloat16_rn(o.w));
        uint2 hv, lv;
        hv.x = pack2bf(hx, hy);             hv.y = pack2bf(hz, hw);
        lv.x = pack2bf(o.x - hx, o.y - hy); lv.y = pack2bf(o.z - hz, o.w - hw);
        ((uint2*)g_xhi)[t * 256 + tid] = hv;
        ((uint2*)g_xlo)[t * 256 + tid] = lv;
    }
}

// ============================================================
// Kernel 2: bf16-split GEMM (mma.sync) + fused mix epilogue
//   CTA 128x128, 8 warps, GK=32/stage, 3-stage cp.async,
//   32KB/stage -> 96KB smem -> 2 CTAs/SM.
// ============================================================
#define GM 128
#define GN 128
#define GK 32
#define ST_AHI 0
#define ST_ALO 8192
#define ST_BHI 16384
#define ST_BLO 24576
#define STAGE_BYTES 32768
#define GEMM_SMEM (3 * STAGE_BYTES)
#define EP_YS   0
#define EP_HRES 69632
#define EP_HPST 77824

__device__ __forceinline__ void load_stage(
    uint32_t sstage, int tid, int m0, int n0, int k0,
    const __nv_bfloat16* __restrict__ Ahi, const __nv_bfloat16* __restrict__ Alo,
    const __nv_bfloat16* __restrict__ Bhi, const __nv_bfloat16* __restrict__ Blo)
{
    // 4 matrices x 128 rows x 4 chunks(16B) = 2048 cp16; 8 per thread
    #pragma unroll
    for (int j = 0; j < 8; j++) {
        int i = tid + (j << 8);
        int mat = i >> 9;                 // 0:Ahi 1:Alo 2:Bhi 3:Blo
        int w = i & 511;
        int r = w >> 2, c = w & 3;
        uint32_t so = SW64((uint32_t)(r * 64 + c * 16));
        const __nv_bfloat16* src;
        size_t go;
        if (mat < 2) {
            src = (mat == 0) ? Ahi : Alo;
            go = (size_t)(m0 + r) * HID + k0 + c * 8;
        } else {
            src = (mat == 2) ? Bhi : Blo;
            go = (size_t)(n0 + r) * HID + k0 + c * 8;
        }
        cp16(sstage + mat * 8192 + so, src + go);
    }
}

__global__ __launch_bounds__(256, 2)
void gemm_tc_kernel(const __nv_bfloat16* __restrict__ Ahi,
                    const __nv_bfloat16* __restrict__ Alo,
                    const __nv_bfloat16* __restrict__ Bhi,
                    const __nv_bfloat16* __restrict__ Blo,
                    const float* __restrict__ x,
                    float* __restrict__ out)
{
    extern __shared__ __align__(16) char smem[];
    uint32_t sbase = smem_to_u32(smem);
    const int tid = threadIdx.x, wid = tid >> 5, lane = tid & 31;
    const int wm = wid & 3, wn = wid >> 2;
    const int m0 = blockIdx.y * GM, n0 = blockIdx.x * GN;

    float acc[2][8][4];
    #pragma unroll
    for (int h = 0; h < 2; h++)
        #pragma unroll
        for (int g = 0; g < 8; g++)
            #pragma unroll
            for (int q = 0; q < 4; q++) acc[h][g][q] = 0.f;

    const int a_row = (lane & 15);
    const int a_kx  = ((lane >> 4) & 1) * 16;
    const int b_row = (lane & 7) + ((lane >> 4) & 1) * 8;
    const int b_kx  = ((lane >> 3) & 1) * 16;

    load_stage(sbase, tid, m0, n0, 0, Ahi, Alo, Bhi, Blo);
    asm volatile("cp.async.commit_group;" ::: "memory");
    load_stage(sbase + STAGE_BYTES, tid, m0, n0, GK, Ahi, Alo, Bhi, Blo);
    asm volatile("cp.async.commit_group;" ::: "memory");

    const int NITER = HID / GK;   // 32
    for (int i = 0; i < NITER; i++) {
        if (i < NITER - 1) asm volatile("cp.async.wait_group 1;" ::: "memory");
        else               asm volatile("cp.async.wait_group 0;" ::: "memory");
        __syncthreads();
        if (i + 2 < NITER) {
            load_stage(sbase + ((i + 2) % 3) * STAGE_BYTES, tid, m0, n0, (i + 2) * GK,
                       Ahi, Alo, Bhi, Blo);
            asm volatile("cp.async.commit_group;" ::: "memory");
        }

        uint32_t stg = sbase + (i % 3) * STAGE_BYTES;
        #pragma unroll
        for (int kk = 0; kk < 2; kk++) {
            const int kb = kk * 32;
            uint32_t ah[2][4], al[2][4];
            #pragma unroll
            for (int h = 0; h < 2; h++) {
                uint32_t off = SW64((uint32_t)((32 * wm + 16 * h + a_row) * 64 + kb + a_kx));
                ldsm_x4(ah[h][0], ah[h][1], ah[h][2], ah[h][3], stg + ST_AHI + off);
                ldsm_x4(al[h][0], al[h][1], al[h][2], al[h][3], stg + ST_ALO + off);
            }
            #pragma unroll
            for (int g = 0; g < 4; g++) {
                uint32_t bh[4], bl[4];
                uint32_t off = SW64((uint32_t)((64 * wn + 16 * g + b_row) * 64 + kb + b_kx));
                ldsm_x4(bh[0], bh[1], bh[2], bh[3], stg + ST_BHI + off);
                ldsm_x4(bl[0], bl[1], bl[2], bl[3], stg + ST_BLO + off);
                #pragma unroll
                for (int h = 0; h < 2; h++)
                    #pragma unroll
                    for (int half = 0; half < 2; half++) {
                        int ng = g * 2 + half;
                        mma16816(acc[h][ng], ah[h], &bh[2 * half]);
                        mma16816(acc[h][ng], ah[h], &bl[2 * half]);
                        mma16816(acc[h][ng], al[h], &bh[2 * half]);
                    }
            }
        }
    }

    // ================== fused mix epilogue ==================
    __syncthreads();
    float* ys  = (float*)(smem + EP_YS);   // [128][132]
    float* shr = (float*)(smem + EP_HRES); // [128][16]
    float* shp = (float*)(smem + EP_HPST); // [128][4]

    {
        const int r0 = 32 * wm + (lane >> 2);
        const int c0 = 64 * wn + (lane & 3) * 2;
        #pragma unroll
        for (int h = 0; h < 2; h++)
            #pragma unroll
            for (int ng = 0; ng < 8; ng++) {
                int rr = r0 + 16 * h, cc = c0 + 8 * ng;
                *(float2*)&ys[rr * 132 + cc]       = make_float2(acc[h][ng][0], acc[h][ng][1]);
                *(float2*)&ys[(rr + 8) * 132 + cc] = make_float2(acc[h][ng][2], acc[h][ng][3]);
            }
    }
    #pragma unroll
    for (int j = 0; j < 8; j++) shr[tid + j * 256] = g_Hres[(size_t)m0 * 16 + tid + j * 256];
    #pragma unroll
    for (int j = 0; j < 2; j++) shp[tid + j * 256] = g_Hpost[(size_t)m0 * 4 + tid + j * 256];
    __syncthreads();

    const int col4 = lane;
    #pragma unroll 2
    for (int it = 0; it < 16; it++) {
        const int trow = wid + 8 * it;
        const size_t t = (size_t)(m0 + trow);
        const float* hr = shr + trow * 16;
        const float p0 = shp[trow * 4 + 0], p1 = shp[trow * 4 + 1];
        const float p2 = shp[trow * 4 + 2], p3 = shp[trow * 4 + 3];
        float4 y4 = *(const float4*)&ys[trow * 132 + col4 * 4];
        const float* xb = x + t * D + n0 + col4 * 4;
        float4 xi0 = *(const float4*)(xb);
        float4 xi1 = *(const float4*)(xb + 1024);
        float4 xi2 = *(const float4*)(xb + 2048);
        float4 xi3 = *(const float4*)(xb + 3072);
        float* ob = out + t * D + n0 + col4 * 4;
        #pragma unroll
        for (int o = 0; o < 4; o++) {
            const float h0 = hr[o * 4 + 0], h1 = hr[o * 4 + 1];
            const float h2 = hr[o * 4 + 2], h3 = hr[o * 4 + 3];
            const float p = (o == 0) ? p0 : (o == 1) ? p1 : (o == 2) ? p2 : p3;
            float4 r;
            r.x = h0 * xi0.x + h1 * xi1.x + h2 * xi2.x + h3 * xi3.x + p * y4.x;
            r.y = h0 * xi0.y + h1 * xi1.y + h2 * xi2.y + h3 * xi3.y + p * y4.y;
            r.z = h0 * xi0.z + h1 * xi1.z + h2 * xi2.z + h3 * xi3.z + p * y4.z;
            r.w = h0 * xi0.w + h1 * xi1.w + h2 * xi2.w + h3 * xi3.w + p * y4.w;
            *(float4*)(ob + o * 1024) = r;
        }
    }
}

// ============================================================
extern "C" void kernel_launch(void* const* d_in, const int* in_sizes, int n_in,
                              void* d_out, int out_size)
{
    const float* x      = (const float*)d_in[0];
    const float* rmsw   = (const float*)d_in[1];
    const float* Wpre   = (const float*)d_in[2];
    const float* Wpost  = (const float*)d_in[3];
    const float* Wres   = (const float*)d_in[4];
    const float* bpre   = (const float*)d_in[5];
    const float* bpost  = (const float*)d_in[6];
    const float* bres   = (const float*)d_in[7];
    const float* apre   = (const float*)d_in[8];
    const float* apost  = (const float*)d_in[9];
    const float* ares   = (const float*)d_in[10];
    const float* Wsub   = (const float*)d_in[11];
    float* out = (float*)d_out;

    __nv_bfloat16 *xhi_p, *xlo_p, *whi_p, *wlo_p;
    cudaGetSymbolAddress((void**)&xhi_p, g_xhi);
    cudaGetSymbolAddress((void**)&xlo_p, g_xlo);
    cudaGetSymbolAddress((void**)&whi_p, g_whi);
    cudaGetSymbolAddress((void**)&wlo_p, g_wlo);

    cudaFuncSetAttribute(gemm_tc_kernel,
                         cudaFuncAttributeMaxDynamicSharedMemorySize, GEMM_SMEM);
    cudaFuncSetAttribute(gates_kernel,
                         cudaFuncAttributeMaxDynamicSharedMemorySize, GATES_SMEM);

    wprep_kernel<<<NW * D / 256, 256>>>(Wpre, Wpost, Wres, rmsw);
    wsplit_kernel<<<HID * HID / 4 / 256, 256>>>(Wsub);
    gates_kernel<<<T_TOKENS / TOKB, 256, GATES_SMEM>>>(x, bpre, bpost, bres,
                                                       apre, apost, ares);
    gemm_tc_kernel<<<dim3(HID / GN, T_TOKENS / GM), 256, GEMM_SMEM>>>(
        xhi_p, xlo_p, whi_p, wlo_p, x, out);
}